// round 8
// baseline (speedup 1.0000x reference)
#include <cuda_runtime.h>

// PLNet expansion: out[pp][n,k,i,j,y,x] =
//   0.5*cor0[ij]*cork[ij] * cen0[yx]*cenk[yx]
//   * cor[23+y][ij]*cor[37+x][ij] * cen[23+i][yx]*cen[37+j][yx]
// cor = corner(pp&1), cen = center(pp>>1). Input (n,204,14,14).
//
// R6 k-pair structure + __stcs streaming stores.
// Block: (k-pair {bx, bx+10}, n=by, i-chunk {2bz, 2bz+1}), 196 threads
// = 4 pp x 49 quads. Each inner iteration emits TWO STG.128 (k and k+10)
// from 4 LDS.64: Wd float2 tables (a-folded, per k) + V float2 loads.

__global__ __launch_bounds__(196)
void plnet_kernel(const float* __restrict__ in, float* __restrict__ out)
{
    const int k  = blockIdx.x;        // 0..9 -> output k and k+10
    const int n  = blockIdx.y;        // 0..31
    const int i0 = blockIdx.z * 2;    // 0,2,...,12
    const int t  = threadIdx.x;

    // Wd[cc][kk][rij][y] = a * (cor[23+y], cor[24+y])   (y 0..13, pad 15)
    // V[cc][rij][x]      = cor[37+x]
    __shared__ float2 Wd_s[2][2][28][15];
    __shared__ float  V_s[2][28][14];
    __shared__ float  a_s[2][2][28];

    const float* nb = in + n * (204 * 196);

    // a = 0.5*cor0*cork per (cc, kk, rij)
    if (t < 112) {
        const int cc  = t / 56;
        const int r   = t - cc * 56;
        const int kk  = r / 28;
        const int rij = r - kk * 28;
        const int ij  = i0 * 14 + rij;
        const float* cor = nb + cc * (51 * 196);
        a_s[cc][kk][rij] = 0.5f * cor[ij] * cor[(1 + k + 10 * kk) * 196 + ij];
    }
    __syncthreads();

    // V build: 2cc x 28rij x 14x = 784 items (rij fastest -> coalesced LDG)
    #pragma unroll
    for (int p = 0; p < 784; p += 196) {
        const int id  = p + t;
        const int rij = id % 28;
        const int tmp = id / 28;
        const int x   = tmp % 14;
        const int cc  = tmp / 14;
        const int ij  = i0 * 14 + rij;
        V_s[cc][rij][x] = nb[cc * (51 * 196) + (37 + x) * 196 + ij];
    }
    // Wd build: 2cc x 2kk x 28rij x 14y = 1568 items
    #pragma unroll
    for (int p = 0; p < 1568; p += 196) {
        const int id  = p + t;
        const int rij = id % 28;
        const int tmp = id / 28;       // 0..55
        const int y   = tmp % 14;
        const int t2  = tmp / 14;      // 0..3 = kk + 2*cc
        const int kk  = t2 & 1;
        const int cc  = t2 >> 1;
        const int ij  = i0 * 14 + rij;
        const float* cor = nb + cc * (51 * 196);
        const float a  = a_s[cc][kk][rij];
        Wd_s[cc][kk][rij][y] = make_float2(a * cor[(23 + y) * 196 + ij],
                                           a * cor[(24 + y) * 196 + ij]);
    }

    // per-thread setup
    const int pp = t / 49;
    const int q  = t - pp * 49;
    const int cc = pp & 1;
    const int ss = pp >> 1;
    const int e0 = q * 4;             // plane base (y*14+x), 16B aligned
    const int y0 = e0 / 14;
    const int x0 = e0 - y0 * 14;      // even, 0..12
    const bool cross = (x0 == 12);    // elems 2,3 wrap to (y0+1, x=0,1)
    const int vxo = cross ? 0 : x0 + 2;

    const float* cen = nb + (102 + ss * 51) * 196;
    const float4 c0  = *(const float4*)(cen + e0);
    const float4 ck1 = *(const float4*)(cen + (1 + k) * 196 + e0);
    const float4 ck2 = *(const float4*)(cen + (11 + k) * 196 + e0);
    const float b0a = c0.x * ck1.x, b1a = c0.y * ck1.y, b2a = c0.z * ck1.z, b3a = c0.w * ck1.w;
    const float b0b = c0.x * ck2.x, b1b = c0.y * ck2.y, b2b = c0.z * ck2.z, b3b = c0.w * ck2.w;

    __syncthreads();

    float* op1 = out + (size_t)((pp * 32 + n) * 20 + k) * 38416
                     + (size_t)i0 * 2744 + e0;
    float* op2 = op1 + (size_t)10 * 38416;

    const float2 (*Wc1)[15] = Wd_s[cc][0];
    const float2 (*Wc2)[15] = Wd_s[cc][1];
    const float  (*Vc)[14]  = V_s[cc];

    #pragma unroll
    for (int jb = 0; jb < 14; jb += 7) {
        float4 L[7];
        #pragma unroll
        for (int j = 0; j < 7; ++j)
            L[j] = *(const float4*)(cen + (37 + jb + j) * 196 + e0);

        #pragma unroll
        for (int il = 0; il < 2; ++il) {
            const float4 sx = *(const float4*)(cen + (23 + i0 + il) * 196 + e0);
            const float r0a = b0a * sx.x, r1a = b1a * sx.y, r2a = b2a * sx.z, r3a = b3a * sx.w;
            const float r0b = b0b * sx.x, r1b = b1b * sx.y, r2b = b2b * sx.z, r3b = b3b * sx.w;

            const int rij0 = il * 14 + jb;
            float* o1 = op1 + (size_t)il * 2744 + (size_t)jb * 196;
            float* o2 = op2 + (size_t)il * 2744 + (size_t)jb * 196;

            #pragma unroll
            for (int j = 0; j < 7; ++j) {
                const float2 w1 = Wc1[rij0 + j][y0];
                const float2 w2 = Wc2[rij0 + j][y0];
                const float wlo1 = w1.x, whi1 = cross ? w1.y : w1.x;
                const float wlo2 = w2.x, whi2 = cross ? w2.y : w2.x;
                const float* vr = Vc[rij0 + j];
                const float2 vA = *(const float2*)(vr + x0);
                const float2 vB = *(const float2*)(vr + vxo);

                const float g0 = r0a * L[j].x, g1 = r1a * L[j].y;
                const float g2 = r2a * L[j].z, g3 = r3a * L[j].w;
                const float h0 = r0b * L[j].x, h1 = r1b * L[j].y;
                const float h2 = r2b * L[j].z, h3 = r3b * L[j].w;

                float4 oA;
                oA.x = (wlo1 * vA.x) * g0;
                oA.y = (wlo1 * vA.y) * g1;
                oA.z = (whi1 * vB.x) * g2;
                oA.w = (whi1 * vB.y) * g3;
                __stcs((float4*)(o1 + j * 196), oA);

                float4 oB;
                oB.x = (wlo2 * vA.x) * h0;
                oB.y = (wlo2 * vA.y) * h1;
                oB.z = (whi2 * vB.x) * h2;
                oB.w = (whi2 * vB.y) * h3;
                __stcs((float4*)(o2 + j * 196), oB);
            }
        }
    }
}

extern "C" void kernel_launch(void* const* d_in, const int* in_sizes, int n_in,
                              void* d_out, int out_size)
{
    const float* in = (const float*)d_in[0];
    float* out = (float*)d_out;
    dim3 grid(10, 32, 7);
    plnet_kernel<<<grid, 196>>>(in, out);
}

// round 9
// speedup vs baseline: 1.0519x; 1.0519x over previous
#include <cuda_runtime.h>

// PLNet expansion: out[pp][n,k,i,j,y,x] =
//   0.5*cor0[ij]*cork[ij] * cen0[yx]*cenk[yx]
//   * cor[23+y][ij]*cor[37+x][ij] * cen[23+i][yx]*cen[37+j][yx]
// cor = corner(pp&1), cen = center(pp>>1). Input (n,204,14,14).
//
// k-pair + stcs + FULL grid: block = (k-pair {bx,bx+10}, n=by, i=bz),
// grid 10x32x14 = 4480 blocks, 196 threads = 4 pp x 49 quads.
// Inner iteration: 2 LDS.64 (Wd k-pair) + 2 LDS.64 (V) -> 2 STG.128.
// sx / b products fully hoisted (single i per block).

__global__ __launch_bounds__(196)
void plnet_kernel(const float* __restrict__ in, float* __restrict__ out)
{
    const int k  = blockIdx.x;     // 0..9 -> output k and k+10
    const int n  = blockIdx.y;     // 0..31
    const int i0 = blockIdx.z;     // 0..13
    const int t  = threadIdx.x;

    // Wd[cc][kk][j][y] = a * (cor[23+y], cor[24+y])  (pad 15; .y of y=13 unused)
    // V[cc][j][x]      = cor[37+x]   (row stride 14 floats = 56B, 8B-aligned)
    __shared__ float2 Wd_s[2][2][14][15];
    __shared__ float  V_s[2][14][14];
    __shared__ float  a_s[2][2][14];

    const float* nb = in + n * (204 * 196);

    // a = 0.5*cor0*cork per (cc, kk, j)
    if (t < 56) {
        const int cc  = t / 28;
        const int r   = t - cc * 28;
        const int kk  = r / 14;
        const int rij = r - kk * 14;
        const int ij  = i0 * 14 + rij;
        const float* cor = nb + cc * (51 * 196);
        a_s[cc][kk][rij] = 0.5f * cor[ij] * cor[(1 + k + 10 * kk) * 196 + ij];
    }
    __syncthreads();

    // V build: 2cc x 14j x 14x = 392 items (rij fastest -> coalesced)
    for (int id = t; id < 392; id += 196) {
        const int rij = id % 14;
        const int tmp = id / 14;      // 0..27
        const int x   = tmp % 14;
        const int cc  = tmp / 14;
        const int ij  = i0 * 14 + rij;
        V_s[cc][rij][x] = nb[cc * (51 * 196) + (37 + x) * 196 + ij];
    }
    // Wd build: 2cc x 2kk x 14j x 14y = 784 items
    #pragma unroll
    for (int p = 0; p < 784; p += 196) {
        const int id  = p + t;
        const int rij = id % 14;
        const int tmp = id / 14;      // 0..55
        const int y   = tmp % 14;
        const int t2  = tmp / 14;     // 0..3 = kk + 2*cc
        const int kk  = t2 & 1;
        const int cc  = t2 >> 1;
        const int ij  = i0 * 14 + rij;
        const float* cor = nb + cc * (51 * 196);
        const float a  = a_s[cc][kk][rij];
        Wd_s[cc][kk][rij][y] = make_float2(a * cor[(23 + y) * 196 + ij],
                                           a * cor[(24 + y) * 196 + ij]);
    }

    // per-thread setup
    const int pp = t / 49;
    const int q  = t - pp * 49;
    const int cc = pp & 1;
    const int ss = pp >> 1;
    const int e0 = q * 4;             // plane base (y*14+x), 16B aligned
    const int y0 = e0 / 14;
    const int x0 = e0 - y0 * 14;      // even, 0..12
    const bool cross = (x0 == 12);    // elems 2,3 wrap to (y0+1, x=0,1)
    const int vxo = cross ? 0 : x0 + 2;

    const float* cen = nb + (102 + ss * 51) * 196;
    const float4 c0  = *(const float4*)(cen + e0);
    const float4 ck1 = *(const float4*)(cen + (1 + k) * 196 + e0);
    const float4 ck2 = *(const float4*)(cen + (11 + k) * 196 + e0);
    const float4 sx  = *(const float4*)(cen + (23 + i0) * 196 + e0);

    // fully hoisted per-element products (k and k+10)
    const float r0a = c0.x * ck1.x * sx.x, r1a = c0.y * ck1.y * sx.y;
    const float r2a = c0.z * ck1.z * sx.z, r3a = c0.w * ck1.w * sx.w;
    const float r0b = c0.x * ck2.x * sx.x, r1b = c0.y * ck2.y * sx.y;
    const float r2b = c0.z * ck2.z * sx.z, r3b = c0.w * ck2.w * sx.w;

    __syncthreads();

    float* o1 = out + (size_t)((pp * 32 + n) * 20 + k) * 38416
                    + (size_t)i0 * 2744 + e0;
    float* o2 = o1 + (size_t)10 * 38416;

    const float2 (*Wc1)[15] = Wd_s[cc][0];
    const float2 (*Wc2)[15] = Wd_s[cc][1];
    const float  (*Vc)[14]  = V_s[cc];

    #pragma unroll
    for (int jb = 0; jb < 14; jb += 7) {
        float4 L[7];
        #pragma unroll
        for (int j = 0; j < 7; ++j)
            L[j] = *(const float4*)(cen + (37 + jb + j) * 196 + e0);

        #pragma unroll
        for (int j = 0; j < 7; ++j) {
            const int row = jb + j;
            const float2 w1 = Wc1[row][y0];
            const float2 w2 = Wc2[row][y0];
            const float wlo1 = w1.x, whi1 = cross ? w1.y : w1.x;
            const float wlo2 = w2.x, whi2 = cross ? w2.y : w2.x;
            const float* vr = Vc[row];
            const float2 vA = *(const float2*)(vr + x0);
            const float2 vB = *(const float2*)(vr + vxo);

            const float g0 = r0a * L[j].x, g1 = r1a * L[j].y;
            const float g2 = r2a * L[j].z, g3 = r3a * L[j].w;
            const float h0 = r0b * L[j].x, h1 = r1b * L[j].y;
            const float h2 = r2b * L[j].z, h3 = r3b * L[j].w;

            float4 oA;
            oA.x = (wlo1 * vA.x) * g0;
            oA.y = (wlo1 * vA.y) * g1;
            oA.z = (whi1 * vB.x) * g2;
            oA.w = (whi1 * vB.y) * g3;
            __stcs((float4*)(o1 + row * 196), oA);

            float4 oB;
            oB.x = (wlo2 * vA.x) * h0;
            oB.y = (wlo2 * vA.y) * h1;
            oB.z = (whi2 * vB.x) * h2;
            oB.w = (whi2 * vB.y) * h3;
            __stcs((float4*)(o2 + row * 196), oB);
        }
    }
}

extern "C" void kernel_launch(void* const* d_in, const int* in_sizes, int n_in,
                              void* d_out, int out_size)
{
    const float* in = (const float*)d_in[0];
    float* out = (float*)d_out;
    dim3 grid(10, 32, 14);
    plnet_kernel<<<grid, 196>>>(in, out);
}